// round 5
// baseline (speedup 1.0000x reference)
#include <cuda_runtime.h>
#include <math.h>

// ---- static scratch (no-allocation rule) ----
__device__ __align__(16) float g_bufA[50000 * 64];  // H (pre-scaled transform)
__device__ __align__(16) float g_bufB[50000 * 64];  // X ping
__device__ __align__(16) float g_bufC[50000 * 64];  // X pong
__device__ float g_dinv[50000];
__device__ int g_idx[1600000];   // converted int32 indices: [src | dst]
__device__ int g_cnt[50000];     // in-degree histogram
__device__ int g_rowptr[50001];  // CSR row pointers (by dst)
__device__ int g_cursor[50000];  // fill cursors
__device__ int g_col[800000];    // CSR column (src) ids
__device__ int g_is64;

// ---------------------------------------------------------------------------
// Prep: zero the histogram; block 0 also sniffs the index dtype.
// int64 high words (odd positions) are all zero for ids < 50000; int32 data
// has random ids there.
// ---------------------------------------------------------------------------
__global__ void k_prep(const int* __restrict__ w, int n) {
    int i = blockIdx.x * blockDim.x + threadIdx.x;
    if (i < n) g_cnt[i] = 0;
    if (blockIdx.x == 0) {
        __shared__ int any_nz;
        if (threadIdx.x == 0) any_nz = 0;
        __syncthreads();
        int nz = 0;
        for (int k = threadIdx.x; k < 4096; k += blockDim.x)
            if (w[2 * k + 1] != 0) nz = 1;
        if (nz) atomicOr(&any_nz, 1);
        __syncthreads();
        if (threadIdx.x == 0) g_is64 = any_nz ? 0 : 1;
    }
}

// Convert + clamp indices; histogram in-degrees for the dst half.
__global__ void k_convert(const void* __restrict__ ei, int E, int n) {
    int e = blockIdx.x * blockDim.x + threadIdx.x;
    if (e >= 2 * E) return;
    int v;
    if (g_is64)
        v = (int)((const long long*)ei)[e];
    else
        v = ((const int*)ei)[e];
    v = min(max(v, 0), n - 1);
    g_idx[e] = v;
    if (e >= E) atomicAdd(&g_cnt[v], 1);
}

// Single-block exclusive scan of g_cnt -> g_rowptr (+ cursor copy + dinv).
__global__ void k_scan(int n) {
    __shared__ int partial[1024];
    int t = threadIdx.x;
    int per = (n + 1023) / 1024;
    int lo = t * per, hi = min(lo + per, n);
    int s = 0;
    for (int i = lo; i < hi; i++) s += g_cnt[i];
    partial[t] = s;
    __syncthreads();
    for (int off = 1; off < 1024; off <<= 1) {
        int v = partial[t];
        int add = (t >= off) ? partial[t - off] : 0;
        __syncthreads();
        partial[t] = v + add;
        __syncthreads();
    }
    int ex = (t == 0) ? 0 : partial[t - 1];
    for (int i = lo; i < hi; i++) {
        int c = g_cnt[i];
        g_rowptr[i] = ex;
        g_cursor[i] = ex;
        g_dinv[i] = rsqrtf((float)c + 1.0f);  // + self-loop
        ex += c;
    }
    if (t == 0) g_rowptr[n] = partial[1023];
}

__global__ void k_fill(int E) {
    int e = blockIdx.x * blockDim.x + threadIdx.x;
    if (e >= E) return;
    int s = g_idx[e];
    int d = g_idx[E + e];
    int pos = atomicAdd(&g_cursor[d], 1);
    g_col[pos] = s;
}

// ---------------------------------------------------------------------------
// GEMM 64x64: H[i,:] = dinv[i] * (X[i,:] @ W). 128-row tile, 8x4 per thread.
// ---------------------------------------------------------------------------
__global__ __launch_bounds__(256) void k_gemm64(const float* __restrict__ X,
                                                const float* __restrict__ W,
                                                float* __restrict__ H, int n) {
    __shared__ float Xs[64 * 128];  // transposed: Xs[k*128 + r] = X[r][k]
    __shared__ float Ws[64 * 64];   // Ws[k*64 + c]
    int tid = threadIdx.x;
    int rbase = blockIdx.x * 128;

    for (int i = tid; i < 1024; i += 256)
        ((float4*)Ws)[i] = ((const float4*)W)[i];
    // load X tile (128 rows x 64 cols), store transposed
    for (int i = tid; i < 2048; i += 256) {
        int r = i >> 4;          // 0..127
        int c4 = (i & 15) << 2;  // 0..60
        int gr = rbase + r;
        float4 v = (gr < n) ? ((const float4*)(X + (size_t)gr * 64))[i & 15]
                            : make_float4(0.f, 0.f, 0.f, 0.f);
        Xs[(c4 + 0) * 128 + r] = v.x;
        Xs[(c4 + 1) * 128 + r] = v.y;
        Xs[(c4 + 2) * 128 + r] = v.z;
        Xs[(c4 + 3) * 128 + r] = v.w;
    }
    __syncthreads();

    int r0 = (tid >> 4) << 3;  // 0..120 (8 rows)
    int c0 = (tid & 15) << 2;  // 0..60  (4 cols)
    float acc[8][4];
#pragma unroll
    for (int i = 0; i < 8; i++)
#pragma unroll
        for (int j = 0; j < 4; j++) acc[i][j] = 0.f;

#pragma unroll 4
    for (int k = 0; k < 64; k++) {
        float4 xa = *(const float4*)&Xs[k * 128 + r0];
        float4 xb = *(const float4*)&Xs[k * 128 + r0 + 4];
        float4 wa = *(const float4*)&Ws[k * 64 + c0];
        float xr[8] = {xa.x, xa.y, xa.z, xa.w, xb.x, xb.y, xb.z, xb.w};
        float wr[4] = {wa.x, wa.y, wa.z, wa.w};
#pragma unroll
        for (int i = 0; i < 8; i++)
#pragma unroll
            for (int j = 0; j < 4; j++) acc[i][j] = fmaf(xr[i], wr[j], acc[i][j]);
    }

#pragma unroll
    for (int i = 0; i < 8; i++) {
        int gr = rbase + r0 + i;
        if (gr < n) {
            float di = g_dinv[gr];
            float4 o = make_float4(acc[i][0] * di, acc[i][1] * di,
                                   acc[i][2] * di, acc[i][3] * di);
            *(float4*)(H + (size_t)gr * 64 + c0) = o;
        }
    }
}

// ---------------------------------------------------------------------------
// GEMM 64x40 (layer 3): writes pre-scaled H.
// ---------------------------------------------------------------------------
__global__ __launch_bounds__(256) void k_gemm40(const float* __restrict__ X,
                                                const float* __restrict__ W,
                                                float* __restrict__ H, int n) {
    __shared__ float Ws[64 * 41];
    __shared__ float Xs[64 * 65];
    int tid = threadIdx.x;
    for (int idx = tid; idx < 64 * 40; idx += 256) {
        int k = idx / 40, c = idx - k * 40;
        Ws[k * 41 + c] = W[idx];
    }
    int r0 = blockIdx.x * 64;
    for (int idx = tid; idx < 64 * 64; idx += 256) {
        int r = idx >> 6, c = idx & 63;
        int gr = r0 + r;
        Xs[r * 65 + c] = (gr < n) ? X[(size_t)gr * 64 + c] : 0.0f;
    }
    __syncthreads();

    int row = tid >> 2;
    int c0 = (tid & 3) * 10;
    float acc[10];
#pragma unroll
    for (int j = 0; j < 10; j++) acc[j] = 0.0f;
#pragma unroll
    for (int k = 0; k < 64; k++) {
        float xv = Xs[row * 65 + k];
        const float* wr = &Ws[k * 41 + c0];
#pragma unroll
        for (int j = 0; j < 10; j++) acc[j] = fmaf(xv, wr[j], acc[j]);
    }
    int gr = r0 + row;
    if (gr < n) {
        float di = g_dinv[gr];
        size_t base = (size_t)gr * 40 + c0;
#pragma unroll
        for (int j = 0; j < 10; j++) H[base + j] = acc[j] * di;
    }
}

// ---------------------------------------------------------------------------
// CSR gather, D=64: HALF-WARP (16 lanes) per node, lane owns float4.
// Warp covers nodes 2*warp and 2*warp+1. 4-deep accumulator MLP.
// ---------------------------------------------------------------------------
__global__ __launch_bounds__(256) void k_gather64(const float* __restrict__ H,
                                                  const float* __restrict__ b,
                                                  float* __restrict__ X, int n) {
    int warp = (blockIdx.x * blockDim.x + threadIdx.x) >> 5;
    int lane = threadIdx.x & 31;
    int sub = lane >> 4;
    int hl = lane & 15;
    int v = warp * 2 + sub;
    if (v >= n) return;
    unsigned hmask = 0xFFFFu << (sub << 4);
    const float4* __restrict__ H4 = (const float4*)H;

    float4 a0 = H4[(size_t)v * 16 + hl];  // self-loop
    float4 a1 = make_float4(0.f, 0.f, 0.f, 0.f);
    float4 a2 = make_float4(0.f, 0.f, 0.f, 0.f);
    float4 a3 = make_float4(0.f, 0.f, 0.f, 0.f);

    int rs = g_rowptr[v], re = g_rowptr[v + 1];
    for (int base = rs; base < re; base += 16) {
        int m = min(16, re - base);
        int cs = (hl < m) ? g_col[base + hl] : 0;
        int j = 0;
        for (; j + 4 <= m; j += 4) {
            int s0 = __shfl_sync(hmask, cs, j + 0, 16);
            int s1 = __shfl_sync(hmask, cs, j + 1, 16);
            int s2 = __shfl_sync(hmask, cs, j + 2, 16);
            int s3 = __shfl_sync(hmask, cs, j + 3, 16);
            float4 h0 = H4[(size_t)s0 * 16 + hl];
            float4 h1 = H4[(size_t)s1 * 16 + hl];
            float4 h2 = H4[(size_t)s2 * 16 + hl];
            float4 h3 = H4[(size_t)s3 * 16 + hl];
            a0.x += h0.x; a0.y += h0.y; a0.z += h0.z; a0.w += h0.w;
            a1.x += h1.x; a1.y += h1.y; a1.z += h1.z; a1.w += h1.w;
            a2.x += h2.x; a2.y += h2.y; a2.z += h2.z; a2.w += h2.w;
            a3.x += h3.x; a3.y += h3.y; a3.z += h3.z; a3.w += h3.w;
        }
        for (; j < m; j++) {
            int s = __shfl_sync(hmask, cs, j, 16);
            float4 h = H4[(size_t)s * 16 + hl];
            a0.x += h.x; a0.y += h.y; a0.z += h.z; a0.w += h.w;
        }
    }
    float di = g_dinv[v];
    float4 bb = ((const float4*)b)[hl];
    float4 o;
    o.x = fmaxf(fmaf(a0.x + a1.x + a2.x + a3.x, di, bb.x), 0.f);
    o.y = fmaxf(fmaf(a0.y + a1.y + a2.y + a3.y, di, bb.y), 0.f);
    o.z = fmaxf(fmaf(a0.z + a1.z + a2.z + a3.z, di, bb.z), 0.f);
    o.w = fmaxf(fmaf(a0.w + a1.w + a2.w + a3.w, di, bb.w), 0.f);
    ((float4*)X)[(size_t)v * 16 + hl] = o;
}

// ---------------------------------------------------------------------------
// CSR gather, D=40 + fused relu + log_softmax. Half-warp per node, lanes
// hl<10 own float4 (40 floats).
// ---------------------------------------------------------------------------
__global__ __launch_bounds__(256) void k_gather40(const float* __restrict__ H,
                                                  const float* __restrict__ b,
                                                  float* __restrict__ out, int n) {
    int warp = (blockIdx.x * blockDim.x + threadIdx.x) >> 5;
    int lane = threadIdx.x & 31;
    int sub = lane >> 4;
    int hl = lane & 15;
    int v = warp * 2 + sub;
    if (v >= n) return;
    unsigned hmask = 0xFFFFu << (sub << 4);
    bool act = hl < 10;
    const float4* __restrict__ H4 = (const float4*)H;

    float4 a0 = act ? H4[(size_t)v * 10 + hl] : make_float4(0.f, 0.f, 0.f, 0.f);
    float4 a1 = make_float4(0.f, 0.f, 0.f, 0.f);

    int rs = g_rowptr[v], re = g_rowptr[v + 1];
    for (int base = rs; base < re; base += 16) {
        int m = min(16, re - base);
        int cs = (hl < m) ? g_col[base + hl] : 0;
        int j = 0;
        for (; j + 2 <= m; j += 2) {
            int s0 = __shfl_sync(hmask, cs, j + 0, 16);
            int s1 = __shfl_sync(hmask, cs, j + 1, 16);
            if (act) {
                float4 h0 = H4[(size_t)s0 * 10 + hl];
                float4 h1 = H4[(size_t)s1 * 10 + hl];
                a0.x += h0.x; a0.y += h0.y; a0.z += h0.z; a0.w += h0.w;
                a1.x += h1.x; a1.y += h1.y; a1.z += h1.z; a1.w += h1.w;
            }
        }
        if (j < m) {
            int s = __shfl_sync(hmask, cs, j, 16);
            if (act) {
                float4 h = H4[(size_t)s * 10 + hl];
                a0.x += h.x; a0.y += h.y; a0.z += h.z; a0.w += h.w;
            }
        }
    }
    float di = g_dinv[v];
    float4 o = make_float4(-3.4e38f, -3.4e38f, -3.4e38f, -3.4e38f);
    if (act) {
        float4 bb = ((const float4*)b)[hl];
        o.x = fmaxf(fmaf(a0.x + a1.x, di, bb.x), 0.f);
        o.y = fmaxf(fmaf(a0.y + a1.y, di, bb.y), 0.f);
        o.z = fmaxf(fmaf(a0.z + a1.z, di, bb.z), 0.f);
        o.w = fmaxf(fmaf(a0.w + a1.w, di, bb.w), 0.f);
    }
    float mx = fmaxf(fmaxf(o.x, o.y), fmaxf(o.z, o.w));
#pragma unroll
    for (int off = 8; off; off >>= 1)
        mx = fmaxf(mx, __shfl_xor_sync(hmask, mx, off, 16));
    float sm = act ? (expf(o.x - mx) + expf(o.y - mx) + expf(o.z - mx) +
                      expf(o.w - mx))
                   : 0.f;
#pragma unroll
    for (int off = 8; off; off >>= 1)
        sm += __shfl_xor_sync(hmask, sm, off, 16);
    float c = mx + logf(sm);
    if (act) {
        float4 r = make_float4(o.x - c, o.y - c, o.z - c, o.w - c);
        ((float4*)out)[(size_t)v * 10 + hl] = r;
    }
}

// ---------------------------------------------------------------------------
// Launch
// ---------------------------------------------------------------------------
extern "C" void kernel_launch(void* const* d_in, const int* in_sizes, int n_in,
                              void* d_out, int out_size) {
    const float* x = (const float*)d_in[0];
    const void* ei = d_in[1];
    const float* W1 = (const float*)d_in[2];
    const float* b1 = (const float*)d_in[3];
    const float* W2 = (const float*)d_in[4];
    const float* b2 = (const float*)d_in[5];
    const float* W3 = (const float*)d_in[6];
    const float* b3 = (const float*)d_in[7];
    float* out = (float*)d_out;

    int n = in_sizes[0] / 64;
    int E = in_sizes[1] / 2;

    static float* A = nullptr;
    static float* B = nullptr;
    static float* C = nullptr;
    if (!A) {
        cudaGetSymbolAddress((void**)&A, g_bufA);
        cudaGetSymbolAddress((void**)&B, g_bufB);
        cudaGetSymbolAddress((void**)&C, g_bufC);
    }

    int nb = (n + 255) / 256;
    int eb = (E + 255) / 256;
    int cb = (2 * E + 255) / 256;
    int tiles128 = (n + 127) / 128;
    int tiles64 = (n + 63) / 64;
    int gb = (((n + 1) / 2) * 32 + 255) / 256;  // half-warp-per-node grids

    // CSR build
    k_prep<<<nb, 256>>>((const int*)ei, n);
    k_convert<<<cb, 256>>>(ei, E, n);
    k_scan<<<1, 1024>>>(n);
    k_fill<<<eb, 256>>>(E);

    // Layer 1
    k_gemm64<<<tiles128, 256>>>(x, W1, A, n);
    k_gather64<<<gb, 256>>>(A, b1, C, n);
    // Layer 2
    k_gemm64<<<tiles128, 256>>>(C, W2, A, n);
    k_gather64<<<gb, 256>>>(A, b2, B, n);
    // Layer 3
    k_gemm40<<<tiles64, 256>>>(B, W3, A, n);
    k_gather40<<<gb, 256>>>(A, b3, out, n);
}